// round 2
// baseline (speedup 1.0000x reference)
#include <cuda_runtime.h>
#include <cstdint>

#define N_UNARY 128
#define NB      64
#define DROW    (2 * N_UNARY + NB)   // 320 floats per deltas row
#define EPW     4                    // edges per warp

// ---------------------------------------------------------------------------
// Kernel 1: zero the `out` accumulator region (N * 128 floats).
// ---------------------------------------------------------------------------
__global__ void zero_out_kernel(float4* __restrict__ out4, long long n4) {
    long long i = (long long)blockIdx.x * blockDim.x + threadIdx.x;
    long long stride = (long long)gridDim.x * blockDim.x;
    for (; i < n4; i += stride) {
        out4[i] = make_float4(0.f, 0.f, 0.f, 0.f);
    }
}

__device__ __forceinline__ void red_add_v4(float* addr, float4 v) {
    asm volatile("red.global.add.v4.f32 [%0], {%1, %2, %3, %4};"
                 :: "l"(addr), "f"(v.x), "f"(v.y), "f"(v.z), "f"(v.w)
                 : "memory");
}

// ---------------------------------------------------------------------------
// Kernel 2: one warp per 4 edges. All loads are issued first (MLP ~10 per
// thread) so the LSU/L1tex queue stays full, then the REDs and b stores
// drain. b handling is full-warp: the 4 rows contribute 64 float4s -> each
// lane moves 2 of them (j = lane and lane+32).
// deltas is read exactly once -> __ldcs (evict-first) keeps it from evicting
// the L2-resident `out` accumulator (51.2 MB << 126 MB L2).
// ---------------------------------------------------------------------------
__global__ void __launch_bounds__(256)
scatter4_kernel(const float* __restrict__ deltas,
                const int*   __restrict__ index1,
                const int*   __restrict__ index2,
                float* __restrict__ out,        // [N, 128]
                float* __restrict__ outB,       // [E, 64]
                int E) {
    int warp_id = (blockIdx.x * blockDim.x + threadIdx.x) >> 5;
    int lane = threadIdx.x & 31;
    int e0 = warp_id * EPW;
    if (e0 >= E) return;

    if (e0 + EPW <= E) {
        const float4* r0 = reinterpret_cast<const float4*>(deltas + (size_t)(e0 + 0) * DROW);
        const float4* r1 = reinterpret_cast<const float4*>(deltas + (size_t)(e0 + 1) * DROW);
        const float4* r2 = reinterpret_cast<const float4*>(deltas + (size_t)(e0 + 2) * DROW);
        const float4* r3 = reinterpret_cast<const float4*>(deltas + (size_t)(e0 + 3) * DROW);

        // ---- front-batched loads (independent -> high MLP) ----
        float4 a0 = __ldcs(r0 + lane);
        float4 a1 = __ldcs(r1 + lane);
        float4 a2 = __ldcs(r2 + lane);
        float4 a3 = __ldcs(r3 + lane);
        float4 c0 = __ldcs(r0 + 32 + lane);
        float4 c1 = __ldcs(r1 + 32 + lane);
        float4 c2 = __ldcs(r2 + 32 + lane);
        float4 c3 = __ldcs(r3 + 32 + lane);

        // b: 4 rows x 16 float4 = 64 items; lane handles j=lane and j=lane+32
        int j0 = lane, j1 = lane + 32;
        const float4* rb0 = reinterpret_cast<const float4*>(
            deltas + (size_t)(e0 + (j0 >> 4)) * DROW) + 64 + (j0 & 15);
        const float4* rb1 = reinterpret_cast<const float4*>(
            deltas + (size_t)(e0 + (j1 >> 4)) * DROW) + 64 + (j1 & 15);
        float4 b0 = __ldcs(rb0);
        float4 b1 = __ldcs(rb1);

        int i1_0 = __ldg(index1 + e0 + 0);
        int i1_1 = __ldg(index1 + e0 + 1);
        int i1_2 = __ldg(index1 + e0 + 2);
        int i1_3 = __ldg(index1 + e0 + 3);
        int i2_0 = __ldg(index2 + e0 + 0);
        int i2_1 = __ldg(index2 + e0 + 1);
        int i2_2 = __ldg(index2 + e0 + 2);
        int i2_3 = __ldg(index2 + e0 + 3);

        // ---- drain: b stores (streaming) + scatter REDs ----
        __stcs(reinterpret_cast<float4*>(outB) + (size_t)(e0 + (j0 >> 4)) * 16 + (j0 & 15), b0);
        __stcs(reinterpret_cast<float4*>(outB) + (size_t)(e0 + (j1 >> 4)) * 16 + (j1 & 15), b1);

        int off = lane * 4;
        red_add_v4(out + (size_t)i1_0 * N_UNARY + off, a0);
        red_add_v4(out + (size_t)i1_1 * N_UNARY + off, a1);
        red_add_v4(out + (size_t)i1_2 * N_UNARY + off, a2);
        red_add_v4(out + (size_t)i1_3 * N_UNARY + off, a3);
        red_add_v4(out + (size_t)i2_0 * N_UNARY + off, c0);
        red_add_v4(out + (size_t)i2_1 * N_UNARY + off, c1);
        red_add_v4(out + (size_t)i2_2 * N_UNARY + off, c2);
        red_add_v4(out + (size_t)i2_3 * N_UNARY + off, c3);
    } else {
        // tail: per-edge fallback
        for (int e = e0; e < E; e++) {
            const float4* row = reinterpret_cast<const float4*>(deltas + (size_t)e * DROW);
            int i1 = __ldg(index1 + e);
            int i2 = __ldg(index2 + e);
            float4 a = __ldcs(row + lane);
            float4 c = __ldcs(row + 32 + lane);
            red_add_v4(out + (size_t)i1 * N_UNARY + lane * 4, a);
            red_add_v4(out + (size_t)i2 * N_UNARY + lane * 4, c);
            if (lane < 16) {
                float4 bb = __ldcs(row + 64 + lane);
                __stcs(reinterpret_cast<float4*>(outB + (size_t)e * NB) + lane, bb);
            }
        }
    }
}

// ---------------------------------------------------------------------------
// Inputs (metadata order): unary [N,128] f32, binary [E,64] f32,
//                          deltas [E,320] f32, index1 [E,1] i32, index2 [E,1] i32
// Output buffer: [ out (N*128 f32) | b (E*64 f32) ]
// ---------------------------------------------------------------------------
extern "C" void kernel_launch(void* const* d_in, const int* in_sizes, int n_in,
                              void* d_out, int out_size) {
    const float* deltas = (const float*)d_in[2];
    const int*   index1 = (const int*)d_in[3];
    const int*   index2 = (const int*)d_in[4];

    int N = in_sizes[0] / N_UNARY;      // 100000
    int E = in_sizes[3];                // 500000

    float* out  = (float*)d_out;
    float* outB = out + (size_t)N * N_UNARY;

    // 1) zero the accumulator region
    long long n4 = (long long)N * N_UNARY / 4;
    int zb = (int)((n4 + 255) / 256);
    if (zb > 65535) zb = 65535;
    zero_out_kernel<<<zb, 256>>>(reinterpret_cast<float4*>(out), n4);

    // 2) scatter-add + b copy: one warp per 4 edges, 8 warps per block
    int warps = (E + EPW - 1) / EPW;
    int blocks = (warps + 7) / 8;
    scatter4_kernel<<<blocks, 256>>>(deltas, index1, index2, out, outB, E);
}

// round 3
// speedup vs baseline: 1.0039x; 1.0039x over previous
#include <cuda_runtime.h>
#include <cstdint>

#define N_UNARY 128
#define NB      64
#define DROW    (2 * N_UNARY + NB)   // 320 floats per deltas row
#define DROW4   (DROW / 4)           // 80 float4 per row

// ---------------------------------------------------------------------------
// Kernel 1: zero the `out` accumulator region (N * 128 floats).
// ---------------------------------------------------------------------------
__global__ void zero_out_kernel(float4* __restrict__ out4, long long n4) {
    long long i = (long long)blockIdx.x * blockDim.x + threadIdx.x;
    long long stride = (long long)gridDim.x * blockDim.x;
    for (; i < n4; i += stride) {
        out4[i] = make_float4(0.f, 0.f, 0.f, 0.f);
    }
}

__device__ __forceinline__ void red_add_v4(float* addr, float4 v) {
    asm volatile("red.global.add.v4.f32 [%0], {%1, %2, %3, %4};"
                 :: "l"(addr), "f"(v.x), "f"(v.y), "f"(v.z), "f"(v.w)
                 : "memory");
}

// ---------------------------------------------------------------------------
// Kernel 2: scatter only (ux/uy). One warp per edge, low regs -> high occ.
// deltas read once -> __ldcs keeps the L2-resident `out` accumulator hot.
// ---------------------------------------------------------------------------
__global__ void __launch_bounds__(256, 8)
scatter_kernel(const float* __restrict__ deltas,
               const int*   __restrict__ index1,
               const int*   __restrict__ index2,
               float* __restrict__ out,        // [N, 128]
               int E) {
    int warp_id = (blockIdx.x * blockDim.x + threadIdx.x) >> 5;
    if (warp_id >= E) return;
    int lane = threadIdx.x & 31;

    const float4* row = reinterpret_cast<const float4*>(deltas + (size_t)warp_id * DROW);

    int i1 = __ldg(index1 + warp_id);
    int i2 = __ldg(index2 + warp_id);

    float4 a = __ldcs(row + lane);        // ux
    float4 c = __ldcs(row + 32 + lane);   // uy

    red_add_v4(out + (size_t)i1 * N_UNARY + lane * 4, a);
    red_add_v4(out + (size_t)i2 * N_UNARY + lane * 4, c);
}

// ---------------------------------------------------------------------------
// Kernel 3: b copy — pure streaming, runs on a forked capture branch so its
// 256 MB of traffic overlaps the RED-throttled scatter kernel.
// thread t -> edge t/16, float4-slot t%16 (16 consecutive threads read a
// contiguous 256B segment = 2 full sectors; fully coalesced).
// ---------------------------------------------------------------------------
__global__ void __launch_bounds__(256)
bcopy_kernel(const float4* __restrict__ deltas4,
             float4* __restrict__ outB4,
             long long total) {            // total = E * 16
    long long i = (long long)blockIdx.x * blockDim.x + threadIdx.x;
    if (i >= total) return;
    long long e = i >> 4;
    int s = (int)(i & 15);
    float4 v = __ldcs(deltas4 + e * DROW4 + 64 + s);
    __stcs(outB4 + i, v);
}

// ---------------------------------------------------------------------------
// Inputs (metadata order): unary [N,128] f32, binary [E,64] f32,
//                          deltas [E,320] f32, index1 [E,1] i32, index2 [E,1] i32
// Output buffer: [ out (N*128 f32) | b (E*64 f32) ]
//
// Graph shape (fork/join via events — capture-legal, no allocs of device mem):
//   main:  zero ──► scatter ─────────┐
//   s2  :  bcopy ────────────────────┴► join
// ---------------------------------------------------------------------------
extern "C" void kernel_launch(void* const* d_in, const int* in_sizes, int n_in,
                              void* d_out, int out_size) {
    const float* deltas = (const float*)d_in[2];
    const int*   index1 = (const int*)d_in[3];
    const int*   index2 = (const int*)d_in[4];

    int N = in_sizes[0] / N_UNARY;      // 100000
    int E = in_sizes[3];                // 500000

    float* out  = (float*)d_out;
    float* outB = out + (size_t)N * N_UNARY;

    // One-time host-side resource init (no device memory involved).
    static cudaStream_t s2 = nullptr;
    static cudaEvent_t  ev_fork = nullptr, ev_join = nullptr;
    if (s2 == nullptr) {
        cudaStreamCreateWithFlags(&s2, cudaStreamNonBlocking);
        cudaEventCreateWithFlags(&ev_fork, cudaEventDisableTiming);
        cudaEventCreateWithFlags(&ev_join, cudaEventDisableTiming);
    }

    // --- fork: bcopy branch ---
    cudaEventRecord(ev_fork, 0);
    cudaStreamWaitEvent(s2, ev_fork, 0);
    long long totalB = (long long)E * 16;
    int bblocks = (int)((totalB + 255) / 256);
    bcopy_kernel<<<bblocks, 256, 0, s2>>>(
        reinterpret_cast<const float4*>(deltas),
        reinterpret_cast<float4*>(outB), totalB);
    cudaEventRecord(ev_join, s2);

    // --- main branch: zero then scatter ---
    long long n4 = (long long)N * N_UNARY / 4;
    int zb = (int)((n4 + 255) / 256);
    if (zb > 65535) zb = 65535;
    zero_out_kernel<<<zb, 256>>>(reinterpret_cast<float4*>(out), n4);

    int blocks = (E + 7) / 8;   // one warp per edge, 8 warps/block
    scatter_kernel<<<blocks, 256>>>(deltas, index1, index2, out, E);

    // --- join ---
    cudaStreamWaitEvent(0, ev_join, 0);
}

// round 4
// speedup vs baseline: 1.0041x; 1.0002x over previous
#include <cuda_runtime.h>
#include <cstdint>

#define N_UNARY 128
#define NB      64
#define DROW    (2 * N_UNARY + NB)   // 320 floats per deltas row
#define DROW4   (DROW / 4)           // 80 float4 per row

// ---------------------------------------------------------------------------
// K1: pure streaming prep — zero the accumulator region AND copy b.
// No atomics, no reuse: the cleanest possible DRAM stream.
//   items [0, nz4)           : zero out4[i]
//   items [nz4, nz4+E*16)    : outB4[j] = deltas4[e*80 + 64 + s]
// 16 consecutive j share an edge row -> 256B contiguous reads, coalesced.
// __ldcs/__stcs keep this traffic evict-first so the zeroed `out` lines
// (normal stores) stay resident in L2 for K2's atomics.
// ---------------------------------------------------------------------------
__global__ void __launch_bounds__(256)
prep_kernel(const float4* __restrict__ deltas4,
            float4* __restrict__ out4,     // N*32 float4
            float4* __restrict__ outB4,    // E*16 float4
            long long nz4, long long total) {
    long long i = (long long)blockIdx.x * blockDim.x + threadIdx.x;
    if (i >= total) return;
    if (i < nz4) {
        out4[i] = make_float4(0.f, 0.f, 0.f, 0.f);
    } else {
        long long j = i - nz4;
        long long e = j >> 4;
        int s = (int)(j & 15);
        float4 v = __ldcs(deltas4 + e * DROW4 + 64 + s);
        __stcs(outB4 + j, v);
    }
}

__device__ __forceinline__ void red_add_v4(float* addr, float4 v) {
    asm volatile("red.global.add.v4.f32 [%0], {%1, %2, %3, %4};"
                 :: "l"(addr), "f"(v.x), "f"(v.y), "f"(v.z), "f"(v.w)
                 : "memory");
}

// ---------------------------------------------------------------------------
// K2: scatter only. One warp per edge (proven best occupancy/DRAM balance).
// Reads the contiguous 1024B ux|uy prefix of each row; streaming loads so the
// L2-resident `out` accumulator stays hot and atomics resolve in L2.
// ---------------------------------------------------------------------------
__global__ void __launch_bounds__(256, 8)
scatter_kernel(const float* __restrict__ deltas,
               const int*   __restrict__ index1,
               const int*   __restrict__ index2,
               float* __restrict__ out,        // [N, 128]
               int E) {
    int warp_id = (blockIdx.x * blockDim.x + threadIdx.x) >> 5;
    if (warp_id >= E) return;
    int lane = threadIdx.x & 31;

    const float4* row = reinterpret_cast<const float4*>(deltas + (size_t)warp_id * DROW);

    int i1 = __ldg(index1 + warp_id);
    int i2 = __ldg(index2 + warp_id);

    float4 a = __ldcs(row + lane);        // ux float4 slot
    float4 c = __ldcs(row + 32 + lane);   // uy float4 slot

    red_add_v4(out + (size_t)i1 * N_UNARY + lane * 4, a);
    red_add_v4(out + (size_t)i2 * N_UNARY + lane * 4, c);
}

// ---------------------------------------------------------------------------
// Inputs (metadata order): unary [N,128] f32, binary [E,64] f32,
//                          deltas [E,320] f32, index1 [E,1] i32, index2 [E,1] i32
// Output buffer: [ out (N*128 f32) | b (E*64 f32) ]
// ---------------------------------------------------------------------------
extern "C" void kernel_launch(void* const* d_in, const int* in_sizes, int n_in,
                              void* d_out, int out_size) {
    const float* deltas = (const float*)d_in[2];
    const int*   index1 = (const int*)d_in[3];
    const int*   index2 = (const int*)d_in[4];

    int N = in_sizes[0] / N_UNARY;      // 100000
    int E = in_sizes[3];                // 500000

    float* out  = (float*)d_out;
    float* outB = out + (size_t)N * N_UNARY;

    // K1: zero + b copy (pure streaming)
    long long nz4   = (long long)N * N_UNARY / 4;   // 3.2M float4
    long long total = nz4 + (long long)E * 16;      // + 8M float4
    int pblocks = (int)((total + 255) / 256);
    prep_kernel<<<pblocks, 256>>>(
        reinterpret_cast<const float4*>(deltas),
        reinterpret_cast<float4*>(out),
        reinterpret_cast<float4*>(outB),
        nz4, total);

    // K2: scatter-add (one warp per edge, 8 warps/block)
    int sblocks = (E + 7) / 8;
    scatter_kernel<<<sblocks, 256>>>(deltas, index1, index2, out, E);
}